// round 1
// baseline (speedup 1.0000x reference)
#include <cuda_runtime.h>
#include <math.h>

// Problem constants
#define CH      64          // channels per head
#define SEQ     1024        // L
#define BT      128         // t-tile per block
#define BS      128         // s-tile per iteration
#define NTILES  (SEQ / BS)  // 8
#define NTHREADS 256

// Shared memory layout (floats)
#define QS_ST 132
#define KS_ST 132
#define VS_ST 128           // swizzled, no pad needed
#define PS_ST 132
#define QS_OFF 0
#define KS_OFF (QS_OFF + CH * QS_ST)                 // 8448
#define VS_OFF (KS_OFF + CH * KS_ST)                 // 16896
#define PS_OFF (VS_OFF + CH * VS_ST)                 // 25088
#define SMEM_FLOATS (PS_OFF + BT * PS_ST)            // 41984
#define SMEM_BYTES (SMEM_FLOATS * 4)                 // 167936

__global__ __launch_bounds__(NTHREADS, 1)
void qkv_attn_kernel(const float* __restrict__ qkv, float* __restrict__ out) {
    extern __shared__ float sm[];

    const int t0 = blockIdx.x * BT;      // t-tile base
    const int hb = blockIdx.y;           // 0..127 (= b*16 + h)
    const int b  = hb >> 4;
    const int h  = hb & 15;

    const float* qg = qkv + ((size_t)b * 3072 + (size_t)h * CH) * SEQ;
    const float* kg = qg + (size_t)1024 * SEQ;
    const float* vg = qg + (size_t)2048 * SEQ;
    float*       og = out + ((size_t)b * 1024 + (size_t)h * CH) * SEQ;

    const int tid = threadIdx.x;
    const int ty  = tid >> 4;   // 0..15  -> t rows ty*8..ty*8+7
    const int tx  = tid & 15;   // 0..15  -> s cols tx*8..  /  c cols tx*4..

    // ---- Load Q tile: Qs[c][t], 64 x 128 ----
    for (int i = tid; i < CH * (BT / 4); i += NTHREADS) {
        int c = i >> 5, t4 = i & 31;
        float4 v = *(const float4*)(qg + (size_t)c * SEQ + t0 + t4 * 4);
        *(float4*)(sm + QS_OFF + c * QS_ST + t4 * 4) = v;
    }

    // ---- Per-thread online-softmax state ----
    float m[8], l[8], o[8][4];
#pragma unroll
    for (int i = 0; i < 8; i++) {
        m[i] = -INFINITY; l[i] = 0.f;
#pragma unroll
        for (int j = 0; j < 4; j++) o[i][j] = 0.f;
    }

    for (int st = 0; st < NTILES; ++st) {
        const int s0 = st * BS;

        // ---- Load K tile (padded) and V tile (XOR-swizzled chunks) ----
        for (int i = tid; i < CH * (BS / 4); i += NTHREADS) {
            int c = i >> 5, s4 = i & 31;
            float4 kv = *(const float4*)(kg + (size_t)c * SEQ + s0 + s4 * 4);
            *(float4*)(sm + KS_OFF + c * KS_ST + s4 * 4) = kv;
            float4 vv = *(const float4*)(vg + (size_t)c * SEQ + s0 + s4 * 4);
            int chunk = s4 ^ ((c >> 2) & 7);
            *(float4*)(sm + VS_OFF + c * VS_ST + chunk * 4) = vv;
        }
        __syncthreads();

        // ---- S = (Q^T K) * 1/8 : 128x128, 8x8 per thread ----
        float acc[8][8];
#pragma unroll
        for (int i = 0; i < 8; i++)
#pragma unroll
            for (int j = 0; j < 8; j++) acc[i][j] = 0.f;

        const float* qrow = sm + QS_OFF + ty * 8;
        const float* krow = sm + KS_OFF + tx * 8;
#pragma unroll 2
        for (int c = 0; c < CH; ++c) {
            float4 a0 = *(const float4*)(qrow + c * QS_ST);
            float4 a1 = *(const float4*)(qrow + c * QS_ST + 4);
            float4 b0 = *(const float4*)(krow + c * KS_ST);
            float4 b1 = *(const float4*)(krow + c * KS_ST + 4);
            float av[8] = {a0.x, a0.y, a0.z, a0.w, a1.x, a1.y, a1.z, a1.w};
            float bv[8] = {b0.x, b0.y, b0.z, b0.w, b1.x, b1.y, b1.z, b1.w};
#pragma unroll
            for (int i = 0; i < 8; i++)
#pragma unroll
                for (int j = 0; j < 8; j++)
                    acc[i][j] = fmaf(av[i], bv[j], acc[i][j]);
        }

        // ---- Online softmax over this s-tile; write P to smem ----
#pragma unroll
        for (int i = 0; i < 8; i++) {
            float rmax = -INFINITY;
#pragma unroll
            for (int j = 0; j < 8; j++) {
                acc[i][j] *= 0.125f;   // scale^2 = 1/sqrt(ch)
                rmax = fmaxf(rmax, acc[i][j]);
            }
            // reduce max across the 16 lanes sharing these t rows
#pragma unroll
            for (int msk = 8; msk > 0; msk >>= 1)
                rmax = fmaxf(rmax, __shfl_xor_sync(0xffffffffu, rmax, msk));

            float mnew  = fmaxf(m[i], rmax);
            float alpha = __expf(m[i] - mnew);   // exp(-inf)=0 on first tile
            m[i] = mnew;

            float rsum = 0.f;
#pragma unroll
            for (int j = 0; j < 8; j++) {
                float p = __expf(acc[i][j] - mnew);
                acc[i][j] = p;
                rsum += p;
            }
            l[i] = l[i] * alpha + rsum;   // per-lane partial row sum
#pragma unroll
            for (int j = 0; j < 4; j++) o[i][j] *= alpha;

            float4 p0 = make_float4(acc[i][0], acc[i][1], acc[i][2], acc[i][3]);
            float4 p1 = make_float4(acc[i][4], acc[i][5], acc[i][6], acc[i][7]);
            *(float4*)(sm + PS_OFF + (ty * 8 + i) * PS_ST + tx * 8)     = p0;
            *(float4*)(sm + PS_OFF + (ty * 8 + i) * PS_ST + tx * 8 + 4) = p1;
        }
        __syncthreads();

        // ---- O += P * V^T (dot along s; both operands s-contiguous) ----
        const float* prow = sm + PS_OFF + (ty * 8) * PS_ST;
#pragma unroll 2
        for (int s4 = 0; s4 < BS / 4; ++s4) {
            float4 pf[8], vf[4];
#pragma unroll
            for (int i = 0; i < 8; i++)
                pf[i] = *(const float4*)(prow + i * PS_ST + s4 * 4);
#pragma unroll
            for (int j = 0; j < 4; j++) {
                int c = tx * 4 + j;
                int chunk = s4 ^ ((c >> 2) & 7);
                vf[j] = *(const float4*)(sm + VS_OFF + c * VS_ST + chunk * 4);
            }
#pragma unroll
            for (int i = 0; i < 8; i++)
#pragma unroll
                for (int j = 0; j < 4; j++) {
                    o[i][j] = fmaf(pf[i].x, vf[j].x, o[i][j]);
                    o[i][j] = fmaf(pf[i].y, vf[j].y, o[i][j]);
                    o[i][j] = fmaf(pf[i].z, vf[j].z, o[i][j]);
                    o[i][j] = fmaf(pf[i].w, vf[j].w, o[i][j]);
                }
        }
        __syncthreads();   // protect Ks/Vs/Ps before next tile's loads
    }

    // ---- Epilogue: finish row sums, normalize ----
#pragma unroll
    for (int i = 0; i < 8; i++) {
        float s = l[i];
#pragma unroll
        for (int msk = 8; msk > 0; msk >>= 1)
            s += __shfl_xor_sync(0xffffffffu, s, msk);
        float inv = 1.f / s;
#pragma unroll
        for (int j = 0; j < 4; j++) o[i][j] *= inv;
    }

    // Stage O[c][t] in smem (reuse P region) for coalesced global stores
#pragma unroll
    for (int i = 0; i < 8; i++)
#pragma unroll
        for (int j = 0; j < 4; j++)
            sm[PS_OFF + (tx * 4 + j) * PS_ST + ty * 8 + i] = o[i][j];
    __syncthreads();

    for (int i = tid; i < CH * (BT / 4); i += NTHREADS) {
        int c = i >> 5, t4 = i & 31;
        float4 v = *(const float4*)(sm + PS_OFF + c * PS_ST + t4 * 4);
        *(float4*)(og + (size_t)c * SEQ + t0 + t4 * 4) = v;
    }
}

extern "C" void kernel_launch(void* const* d_in, const int* in_sizes, int n_in,
                              void* d_out, int out_size) {
    (void)in_sizes; (void)n_in; (void)out_size;
    const float* qkv = (const float*)d_in[0];
    float* out = (float*)d_out;

    cudaFuncSetAttribute(qkv_attn_kernel,
                         cudaFuncAttributeMaxDynamicSharedMemorySize, SMEM_BYTES);

    dim3 grid(SEQ / BT, 128);   // (8 t-tiles, 128 heads)
    qkv_attn_kernel<<<grid, NTHREADS, SMEM_BYTES>>>(qkv, out);
}

// round 3
// speedup vs baseline: 1.2822x; 1.2822x over previous
#include <cuda_runtime.h>
#include <math.h>

#define CH      64
#define SEQ     1024
#define BT      128
#define BS      128
#define NTILES  8
#define NTHREADS 256

#define ST      132                       // smem row stride (floats)
#define QS_OFF  0
#define KS_OFF  (QS_OFF + CH * ST)
#define VS_OFF  (KS_OFF + CH * ST)
#define PS_OFF  (VS_OFF + CH * ST)
#define SMEM_FLOATS (PS_OFF + BT * ST)
#define SMEM_BYTES  (SMEM_FLOATS * 4)     // 168960

__device__ __forceinline__ unsigned tf32_rna(float x) {
    unsigned r;
    asm("cvt.rna.tf32.f32 %0, %1;" : "=r"(r) : "f"(x));
    return r;
}

__device__ __forceinline__ void mma_tf32(float* d, const unsigned* a, const unsigned* b) {
    asm volatile(
        "mma.sync.aligned.m16n8k8.row.col.f32.tf32.tf32.f32 "
        "{%0,%1,%2,%3}, {%4,%5,%6,%7}, {%8,%9}, {%0,%1,%2,%3};\n"
        : "+f"(d[0]), "+f"(d[1]), "+f"(d[2]), "+f"(d[3])
        : "r"(a[0]), "r"(a[1]), "r"(a[2]), "r"(a[3]),
          "r"(b[0]), "r"(b[1]));
}

__global__ __launch_bounds__(NTHREADS, 1)
void qkv_attn_mma(const float* __restrict__ qkv, float* __restrict__ out) {
    extern __shared__ float sm[];

    const int t0 = blockIdx.x * BT;
    const int hb = blockIdx.y;            // b*16 + h
    const int b  = hb >> 4;
    const int h  = hb & 15;

    const float* qg = qkv + ((size_t)b * 3072 + (size_t)h * CH) * SEQ;
    const float* kg = qg + (size_t)1024 * SEQ;
    const float* vg = qg + (size_t)2048 * SEQ;
    float*       og = out + ((size_t)b * 1024 + (size_t)h * CH) * SEQ;

    const int tid  = threadIdx.x;
    const int wid  = tid >> 5;
    const int lane = tid & 31;
    const int g    = lane >> 2;
    const int q4   = lane & 3;
    const int tb   = wid * 16;

    // ---- Load Q tile: Qs[c][t] ----
    for (int i = tid; i < CH * (BT / 4); i += NTHREADS) {
        int c = i >> 5, t4 = i & 31;
        *(float4*)(sm + QS_OFF + c * ST + t4 * 4) =
            *(const float4*)(qg + (size_t)c * SEQ + t0 + t4 * 4);
    }

    float m0 = -INFINITY, m1 = -INFINITY, l0 = 0.f, l1 = 0.f;
    float co[8][4];
#pragma unroll
    for (int nf = 0; nf < 8; nf++)
#pragma unroll
        for (int j = 0; j < 4; j++) co[nf][j] = 0.f;

    for (int st = 0; st < NTILES; ++st) {
        const int s0 = st * BS;

        for (int i = tid; i < CH * (BS / 4); i += NTHREADS) {
            int c = i >> 5, s4 = i & 31;
            *(float4*)(sm + KS_OFF + c * ST + s4 * 4) =
                *(const float4*)(kg + (size_t)c * SEQ + s0 + s4 * 4);
            *(float4*)(sm + VS_OFF + c * ST + s4 * 4) =
                *(const float4*)(vg + (size_t)c * SEQ + s0 + s4 * 4);
        }
        __syncthreads();

        // ---- S = Q^T K  (3xTF32 split) ----
        float cs[16][4];
#pragma unroll
        for (int nf = 0; nf < 16; nf++)
#pragma unroll
            for (int j = 0; j < 4; j++) cs[nf][j] = 0.f;

#pragma unroll
        for (int ks = 0; ks < 8; ks++) {
            const int c0 = ks * 8;
            float a[4];
            a[0] = sm[QS_OFF + (c0 + q4)     * ST + tb + g];
            a[1] = sm[QS_OFF + (c0 + q4)     * ST + tb + g + 8];
            a[2] = sm[QS_OFF + (c0 + q4 + 4) * ST + tb + g];
            a[3] = sm[QS_OFF + (c0 + q4 + 4) * ST + tb + g + 8];
            unsigned ahi[4], alo[4];
#pragma unroll
            for (int j = 0; j < 4; j++) {
                ahi[j] = tf32_rna(a[j]);
                alo[j] = __float_as_uint(a[j] - __uint_as_float(ahi[j]));
            }
#pragma unroll
            for (int nf = 0; nf < 16; nf++) {
                float bf[2];
                bf[0] = sm[KS_OFF + (c0 + q4)     * ST + nf * 8 + g];
                bf[1] = sm[KS_OFF + (c0 + q4 + 4) * ST + nf * 8 + g];
                unsigned bhi[2], blo[2];
#pragma unroll
                for (int j = 0; j < 2; j++) {
                    bhi[j] = tf32_rna(bf[j]);
                    blo[j] = __float_as_uint(bf[j] - __uint_as_float(bhi[j]));
                }
                mma_tf32(cs[nf], ahi, bhi);
                mma_tf32(cs[nf], ahi, blo);
                mma_tf32(cs[nf], alo, bhi);
            }
        }

        // ---- online softmax ----
        float mx0 = -INFINITY, mx1 = -INFINITY;
#pragma unroll
        for (int nf = 0; nf < 16; nf++) {
#pragma unroll
            for (int j = 0; j < 4; j++) cs[nf][j] *= 0.125f;
            mx0 = fmaxf(mx0, fmaxf(cs[nf][0], cs[nf][1]));
            mx1 = fmaxf(mx1, fmaxf(cs[nf][2], cs[nf][3]));
        }
        mx0 = fmaxf(mx0, __shfl_xor_sync(0xffffffffu, mx0, 1));
        mx0 = fmaxf(mx0, __shfl_xor_sync(0xffffffffu, mx0, 2));
        mx1 = fmaxf(mx1, __shfl_xor_sync(0xffffffffu, mx1, 1));
        mx1 = fmaxf(mx1, __shfl_xor_sync(0xffffffffu, mx1, 2));

        const float mn0 = fmaxf(m0, mx0);
        const float mn1 = fmaxf(m1, mx1);
        const float al0 = __expf(m0 - mn0);
        const float al1 = __expf(m1 - mn1);
        m0 = mn0; m1 = mn1;

        float rs0 = 0.f, rs1 = 0.f;
#pragma unroll
        for (int nf = 0; nf < 16; nf++) {
            cs[nf][0] = __expf(cs[nf][0] - mn0);
            cs[nf][1] = __expf(cs[nf][1] - mn0);
            cs[nf][2] = __expf(cs[nf][2] - mn1);
            cs[nf][3] = __expf(cs[nf][3] - mn1);
            rs0 += cs[nf][0] + cs[nf][1];
            rs1 += cs[nf][2] + cs[nf][3];
        }
        l0 = l0 * al0 + rs0;
        l1 = l1 * al1 + rs1;
#pragma unroll
        for (int nf = 0; nf < 8; nf++) {
            co[nf][0] *= al0; co[nf][1] *= al0;
            co[nf][2] *= al1; co[nf][3] *= al1;
        }

        // ---- stage P to smem (warp-private rows) ----
#pragma unroll
        for (int nf = 0; nf < 16; nf++) {
            *(float2*)(sm + PS_OFF + (tb + g)     * ST + nf * 8 + 2 * q4) =
                make_float2(cs[nf][0], cs[nf][1]);
            *(float2*)(sm + PS_OFF + (tb + g + 8) * ST + nf * 8 + 2 * q4) =
                make_float2(cs[nf][2], cs[nf][3]);
        }
        __syncwarp();

        // ---- O += P * V^T  (3xTF32 split) ----
#pragma unroll
        for (int ks = 0; ks < 16; ks++) {
            const int sk = ks * 8;
            float a[4];
            a[0] = sm[PS_OFF + (tb + g)     * ST + sk + q4];
            a[1] = sm[PS_OFF + (tb + g + 8) * ST + sk + q4];
            a[2] = sm[PS_OFF + (tb + g)     * ST + sk + q4 + 4];
            a[3] = sm[PS_OFF + (tb + g + 8) * ST + sk + q4 + 4];
            unsigned ahi[4], alo[4];
#pragma unroll
            for (int j = 0; j < 4; j++) {
                ahi[j] = tf32_rna(a[j]);
                alo[j] = __float_as_uint(a[j] - __uint_as_float(ahi[j]));
            }
#pragma unroll
            for (int nf = 0; nf < 8; nf++) {
                float bf[2];
                bf[0] = sm[VS_OFF + (nf * 8 + g) * ST + sk + q4];
                bf[1] = sm[VS_OFF + (nf * 8 + g) * ST + sk + q4 + 4];
                unsigned bhi[2], blo[2];
#pragma unroll
                for (int j = 0; j < 2; j++) {
                    bhi[j] = tf32_rna(bf[j]);
                    blo[j] = __float_as_uint(bf[j] - __uint_as_float(bhi[j]));
                }
                mma_tf32(co[nf], ahi, bhi);
                mma_tf32(co[nf], ahi, blo);
                mma_tf32(co[nf], alo, bhi);
            }
        }
        __syncthreads();
    }

    // ---- finalize ----
    l0 += __shfl_xor_sync(0xffffffffu, l0, 1);
    l0 += __shfl_xor_sync(0xffffffffu, l0, 2);
    l1 += __shfl_xor_sync(0xffffffffu, l1, 1);
    l1 += __shfl_xor_sync(0xffffffffu, l1, 2);
    const float inv0 = 1.f / l0;
    const float inv1 = 1.f / l1;
#pragma unroll
    for (int nf = 0; nf < 8; nf++) {
        co[nf][0] *= inv0; co[nf][1] *= inv0;
        co[nf][2] *= inv1; co[nf][3] *= inv1;
    }

    // ---- epilogue: O -> [c][t] in smem, then coalesced stores ----
#pragma unroll
    for (int nf = 0; nf < 8; nf++) {
        const int c = nf * 8 + 2 * q4;
        sm[PS_OFF + (c)     * ST + tb + g]     = co[nf][0];
        sm[PS_OFF + (c + 1) * ST + tb + g]     = co[nf][1];
        sm[PS_OFF + (c)     * ST + tb + g + 8] = co[nf][2];
        sm[PS_OFF + (c + 1) * ST + tb + g + 8] = co[nf][3];
    }
    __syncthreads();

    for (int i = tid; i < CH * (BT / 4); i += NTHREADS) {
        int c = i >> 5, t4 = i & 31;
        *(float4*)(og + (size_t)c * SEQ + t0 + t4 * 4) =
            *(const float4*)(sm + PS_OFF + c * ST + t4 * 4);
    }
}

extern "C" void kernel_launch(void* const* d_in, const int* in_sizes, int n_in,
                              void* d_out, int out_size) {
    (void)in_sizes; (void)n_in; (void)out_size;
    const float* qkv = (const float*)d_in[0];
    float* out = (float*)d_out;

    cudaFuncSetAttribute(qkv_attn_mma,
                         cudaFuncAttributeMaxDynamicSharedMemorySize, SMEM_BYTES);

    dim3 grid(SEQ / BT, 128);
    qkv_attn_mma<<<grid, NTHREADS, SMEM_BYTES>>>(qkv, out);
}

// round 4
// speedup vs baseline: 1.3949x; 1.0879x over previous
#include <cuda_runtime.h>
#include <math.h>

#define CH      64
#define SEQ     1024
#define BT      128
#define BS      128
#define NTILES  8
#define NTHREADS 256

// smem word (u32) layout
#define QK_ST   136     // stride for Q2/K2 rows (32 rows of c-pairs, 128 cols + pad)
#define V_ST    68      // stride for V2 rows (64 rows of c, 64 s-pair cols + pad)
#define QHI 0
#define QLO (QHI + 32 * QK_ST)        // 4352
#define KHI (QLO + 32 * QK_ST)        // 8704
#define KLO (KHI + 32 * QK_ST)        // 13056
#define VHI (KLO + 32 * QK_ST)        // 17408
#define VLO (VHI + 64 * V_ST)         // 21760
#define SMEM_WORDS (VLO + 64 * V_ST)  // 26112
#define SMEM_BYTES (SMEM_WORDS * 4)   // 104448
#define OST 132                       // epilogue float stride (reuses QHI region)

// pack two floats into bf16x2 {lo16=f0, hi16=f1}, plus the bf16 residual pair
__device__ __forceinline__ void split2(float f0, float f1, unsigned& hi, unsigned& lo) {
    unsigned h;
    asm("cvt.rn.bf16x2.f32 %0, %1, %2;" : "=r"(h) : "f"(f1), "f"(f0));
    float h0 = __uint_as_float(h << 16);
    float h1 = __uint_as_float(h & 0xffff0000u);
    float r0 = f0 - h0;
    float r1 = f1 - h1;
    asm("cvt.rn.bf16x2.f32 %0, %1, %2;" : "=r"(lo) : "f"(r1), "f"(r0));
    hi = h;
}

__device__ __forceinline__ void mma_bf16(float* d, const unsigned* a, const unsigned* b) {
    asm volatile(
        "mma.sync.aligned.m16n8k16.row.col.f32.bf16.bf16.f32 "
        "{%0,%1,%2,%3}, {%4,%5,%6,%7}, {%8,%9}, {%0,%1,%2,%3};\n"
        : "+f"(d[0]), "+f"(d[1]), "+f"(d[2]), "+f"(d[3])
        : "r"(a[0]), "r"(a[1]), "r"(a[2]), "r"(a[3]), "r"(b[0]), "r"(b[1]));
}

__global__ __launch_bounds__(NTHREADS, 1)
void qkv_attn_bf16x2(const float* __restrict__ qkv, float* __restrict__ out) {
    extern __shared__ unsigned smu[];
    float* smf = (float*)smu;

    const int t0 = blockIdx.x * BT;
    const int hb = blockIdx.y;            // b*16 + h
    const int b  = hb >> 4;
    const int h  = hb & 15;

    const float* qg = qkv + ((size_t)b * 3072 + (size_t)h * CH) * SEQ;
    const float* kg = qg + (size_t)1024 * SEQ;
    const float* vg = qg + (size_t)2048 * SEQ;
    float*       og = out + ((size_t)b * 1024 + (size_t)h * CH) * SEQ;

    const int tid  = threadIdx.x;
    const int wid  = tid >> 5;
    const int lane = tid & 31;
    const int g    = lane >> 2;   // 0..7
    const int q4   = lane & 3;    // 0..3
    const int tb   = wid * 16;

    // ---- Load Q once: pack channel-pairs -> Q2[c2][t] hi/lo ----
    for (int i = tid; i < 1024; i += NTHREADS) {
        int c2 = i >> 5, t4 = (i & 31) * 4;
        float4 x0 = *(const float4*)(qg + (size_t)(2 * c2)     * SEQ + t0 + t4);
        float4 x1 = *(const float4*)(qg + (size_t)(2 * c2 + 1) * SEQ + t0 + t4);
        uint4 hw, lw;
        split2(x0.x, x1.x, hw.x, lw.x);
        split2(x0.y, x1.y, hw.y, lw.y);
        split2(x0.z, x1.z, hw.z, lw.z);
        split2(x0.w, x1.w, hw.w, lw.w);
        *(uint4*)(smu + QHI + c2 * QK_ST + t4) = hw;
        *(uint4*)(smu + QLO + c2 * QK_ST + t4) = lw;
    }

    float m0 = -INFINITY, m1 = -INFINITY, l0 = 0.f, l1 = 0.f;
    float co[8][4];
#pragma unroll
    for (int nf = 0; nf < 8; nf++)
#pragma unroll
        for (int j = 0; j < 4; j++) co[nf][j] = 0.f;

    for (int st = 0; st < NTILES; ++st) {
        const int s0 = st * BS;

        // ---- Load K: channel-pairs -> K2[c2][s] hi/lo ----
        for (int i = tid; i < 1024; i += NTHREADS) {
            int c2 = i >> 5, s4 = (i & 31) * 4;
            float4 x0 = *(const float4*)(kg + (size_t)(2 * c2)     * SEQ + s0 + s4);
            float4 x1 = *(const float4*)(kg + (size_t)(2 * c2 + 1) * SEQ + s0 + s4);
            uint4 hw, lw;
            split2(x0.x, x1.x, hw.x, lw.x);
            split2(x0.y, x1.y, hw.y, lw.y);
            split2(x0.z, x1.z, hw.z, lw.z);
            split2(x0.w, x1.w, hw.w, lw.w);
            *(uint4*)(smu + KHI + c2 * QK_ST + s4) = hw;
            *(uint4*)(smu + KLO + c2 * QK_ST + s4) = lw;
        }
        // ---- Load V: s-pairs -> V2[c][s2] hi/lo ----
        for (int i = tid; i < 2048; i += NTHREADS) {
            int c = i >> 5, s4 = (i & 31) * 4;
            float4 x = *(const float4*)(vg + (size_t)c * SEQ + s0 + s4);
            uint2 hw, lw;
            split2(x.x, x.y, hw.x, lw.x);
            split2(x.z, x.w, hw.y, lw.y);
            *(uint2*)(smu + VHI + c * V_ST + s4 / 2) = hw;
            *(uint2*)(smu + VLO + c * V_ST + s4 / 2) = lw;
        }
        __syncthreads();

        // ---- S = Q^T K  (3-term bf16 split; warp: 16t x 128s) ----
        float cs[16][4];
#pragma unroll
        for (int nf = 0; nf < 16; nf++)
#pragma unroll
            for (int j = 0; j < 4; j++) cs[nf][j] = 0.f;

#pragma unroll
        for (int kb = 0; kb < 4; kb++) {
            const int r0 = kb * 8 + q4;
            unsigned ahi[4], alo[4];
            ahi[0] = smu[QHI + r0 * QK_ST + tb + g];
            ahi[1] = smu[QHI + r0 * QK_ST + tb + g + 8];
            ahi[2] = smu[QHI + (r0 + 4) * QK_ST + tb + g];
            ahi[3] = smu[QHI + (r0 + 4) * QK_ST + tb + g + 8];
            alo[0] = smu[QLO + r0 * QK_ST + tb + g];
            alo[1] = smu[QLO + r0 * QK_ST + tb + g + 8];
            alo[2] = smu[QLO + (r0 + 4) * QK_ST + tb + g];
            alo[3] = smu[QLO + (r0 + 4) * QK_ST + tb + g + 8];
#pragma unroll
            for (int nf = 0; nf < 16; nf++) {
                const int sc = nf * 8 + g;
                unsigned bhi[2], blo[2];
                bhi[0] = smu[KHI + r0 * QK_ST + sc];
                bhi[1] = smu[KHI + (r0 + 4) * QK_ST + sc];
                blo[0] = smu[KLO + r0 * QK_ST + sc];
                blo[1] = smu[KLO + (r0 + 4) * QK_ST + sc];
                mma_bf16(cs[nf], ahi, bhi);
                mma_bf16(cs[nf], ahi, blo);
                mma_bf16(cs[nf], alo, bhi);
            }
        }

        // ---- online softmax (rows tb+g, tb+g+8; quad-partial sums) ----
        float mx0 = -INFINITY, mx1 = -INFINITY;
#pragma unroll
        for (int nf = 0; nf < 16; nf++) {
#pragma unroll
            for (int j = 0; j < 4; j++) cs[nf][j] *= 0.125f;
            mx0 = fmaxf(mx0, fmaxf(cs[nf][0], cs[nf][1]));
            mx1 = fmaxf(mx1, fmaxf(cs[nf][2], cs[nf][3]));
        }
        mx0 = fmaxf(mx0, __shfl_xor_sync(0xffffffffu, mx0, 1));
        mx0 = fmaxf(mx0, __shfl_xor_sync(0xffffffffu, mx0, 2));
        mx1 = fmaxf(mx1, __shfl_xor_sync(0xffffffffu, mx1, 1));
        mx1 = fmaxf(mx1, __shfl_xor_sync(0xffffffffu, mx1, 2));

        const float mn0 = fmaxf(m0, mx0);
        const float mn1 = fmaxf(m1, mx1);
        const float al0 = __expf(m0 - mn0);
        const float al1 = __expf(m1 - mn1);
        m0 = mn0; m1 = mn1;

        float rs0 = 0.f, rs1 = 0.f;
#pragma unroll
        for (int nf = 0; nf < 16; nf++) {
            cs[nf][0] = __expf(cs[nf][0] - mn0);
            cs[nf][1] = __expf(cs[nf][1] - mn0);
            cs[nf][2] = __expf(cs[nf][2] - mn1);
            cs[nf][3] = __expf(cs[nf][3] - mn1);
            rs0 += cs[nf][0] + cs[nf][1];
            rs1 += cs[nf][2] + cs[nf][3];
        }
        l0 = l0 * al0 + rs0;
        l1 = l1 * al1 + rs1;
#pragma unroll
        for (int nf = 0; nf < 8; nf++) {
            co[nf][0] *= al0; co[nf][1] *= al0;
            co[nf][2] *= al1; co[nf][3] *= al1;
        }

        // ---- O += P * V^T : P stays in registers (C-frag == A-frag layout) ----
#pragma unroll
        for (int kb = 0; kb < 8; kb++) {
            unsigned ahi[4], alo[4];
            split2(cs[2 * kb][0],     cs[2 * kb][1],     ahi[0], alo[0]);
            split2(cs[2 * kb][2],     cs[2 * kb][3],     ahi[1], alo[1]);
            split2(cs[2 * kb + 1][0], cs[2 * kb + 1][1], ahi[2], alo[2]);
            split2(cs[2 * kb + 1][2], cs[2 * kb + 1][3], ahi[3], alo[3]);
#pragma unroll
            for (int nf = 0; nf < 8; nf++) {
                const int c = nf * 8 + g;
                unsigned bhi[2], blo[2];
                bhi[0] = smu[VHI + c * V_ST + kb * 8 + q4];
                bhi[1] = smu[VHI + c * V_ST + kb * 8 + 4 + q4];
                blo[0] = smu[VLO + c * V_ST + kb * 8 + q4];
                blo[1] = smu[VLO + c * V_ST + kb * 8 + 4 + q4];
                mma_bf16(co[nf], ahi, bhi);
                mma_bf16(co[nf], ahi, blo);
                mma_bf16(co[nf], alo, bhi);
            }
        }
        __syncthreads();   // K2/V2 (and Q region at the end) free for reuse
    }

    // ---- finalize rows ----
    l0 += __shfl_xor_sync(0xffffffffu, l0, 1);
    l0 += __shfl_xor_sync(0xffffffffu, l0, 2);
    l1 += __shfl_xor_sync(0xffffffffu, l1, 1);
    l1 += __shfl_xor_sync(0xffffffffu, l1, 2);
    const float inv0 = 1.f / l0;
    const float inv1 = 1.f / l1;
#pragma unroll
    for (int nf = 0; nf < 8; nf++) {
        co[nf][0] *= inv0; co[nf][1] *= inv0;
        co[nf][2] *= inv1; co[nf][3] *= inv1;
    }

    // ---- epilogue: stage O as [c][t] floats (reuse Q region), coalesced stores ----
#pragma unroll
    for (int nf = 0; nf < 8; nf++) {
        const int c = nf * 8 + 2 * q4;
        smf[(c)     * OST + tb + g]     = co[nf][0];
        smf[(c + 1) * OST + tb + g]     = co[nf][1];
        smf[(c)     * OST + tb + g + 8] = co[nf][2];
        smf[(c + 1) * OST + tb + g + 8] = co[nf][3];
    }
    __syncthreads();

    for (int i = tid; i < CH * (BT / 4); i += NTHREADS) {
        int c = i >> 5, t4 = i & 31;
        *(float4*)(og + (size_t)c * SEQ + t0 + t4 * 4) =
            *(const float4*)(smf + c * OST + t4 * 4);
    }
}

extern "C" void kernel_launch(void* const* d_in, const int* in_sizes, int n_in,
                              void* d_out, int out_size) {
    (void)in_sizes; (void)n_in; (void)out_size;
    const float* qkv = (const float*)d_in[0];
    float* out = (float*)d_out;

    cudaFuncSetAttribute(qkv_attn_bf16x2,
                         cudaFuncAttributeMaxDynamicSharedMemorySize, SMEM_BYTES);

    dim3 grid(SEQ / BT, 128);
    qkv_attn_bf16x2<<<grid, NTHREADS, SMEM_BYTES>>>(qkv, out);
}

// round 6
// speedup vs baseline: 1.8383x; 1.3178x over previous
#include <cuda_runtime.h>
#include <math.h>

#define CH      64
#define SEQ     1024
#define BT      64
#define BS      128
#define NTILES  8
#define NTHREADS 128

// smem word (u32) layout
#define Q_ST 72
#define K_ST 136
#define V_ST 68
#define QHI 0
#define QLO (QHI + 32 * Q_ST)          // 2304
#define KHI (QLO + 32 * Q_ST)          // 4608
#define KLO (KHI + 32 * K_ST)          // 8960
#define VHI (KLO + 32 * K_ST)          // 13312
#define VLO (VHI + 64 * V_ST)          // 17664
#define SMEM_WORDS (VLO + 64 * V_ST)   // 22016
#define SMEM_BYTES (SMEM_WORDS * 4)    // 88064
#define OST 68                          // epilogue float stride (reuses Q region)

// pack two floats into bf16x2 {lo16=f0, hi16=f1}, plus the bf16 residual pair
__device__ __forceinline__ void split2(float f0, float f1, unsigned& hi, unsigned& lo) {
    unsigned h;
    asm("cvt.rn.bf16x2.f32 %0, %1, %2;" : "=r"(h) : "f"(f1), "f"(f0));
    float h0 = __uint_as_float(h << 16);
    float h1 = __uint_as_float(h & 0xffff0000u);
    float r0 = f0 - h0;
    float r1 = f1 - h1;
    asm("cvt.rn.bf16x2.f32 %0, %1, %2;" : "=r"(lo) : "f"(r1), "f"(r0));
    hi = h;
}

__device__ __forceinline__ void mma_bf16(float* d, const unsigned* a, const unsigned* b) {
    asm volatile(
        "mma.sync.aligned.m16n8k16.row.col.f32.bf16.bf16.f32 "
        "{%0,%1,%2,%3}, {%4,%5,%6,%7}, {%8,%9}, {%0,%1,%2,%3};\n"
        : "+f"(d[0]), "+f"(d[1]), "+f"(d[2]), "+f"(d[3])
        : "r"(a[0]), "r"(a[1]), "r"(a[2]), "r"(a[3]), "r"(b[0]), "r"(b[1]));
}

__global__ __launch_bounds__(NTHREADS, 2)
void qkv_attn_v6(const float* __restrict__ qkv, float* __restrict__ out) {
    extern __shared__ unsigned smu[];
    float* smf = (float*)smu;

    const int t0 = blockIdx.x * BT;
    const int hb = blockIdx.y;            // b*16 + h
    const int b  = hb >> 4;
    const int h  = hb & 15;

    const float* qg = qkv + ((size_t)b * 3072 + (size_t)h * CH) * SEQ;
    const float* kg = qg + (size_t)1024 * SEQ;
    const float* vg = qg + (size_t)2048 * SEQ;
    float*       og = out + ((size_t)b * 1024 + (size_t)h * CH) * SEQ;

    const int tid  = threadIdx.x;
    const int wid  = tid >> 5;     // 0..3
    const int lane = tid & 31;
    const int g    = lane >> 2;    // 0..7
    const int q4   = lane & 3;     // 0..3
    const int tb   = wid * 16;

    // ---- Load Q once: channel-pairs -> Q2[c2][t] hi/lo  (32 x 64) ----
    for (int i = tid; i < 512; i += NTHREADS) {
        int c2 = i >> 4, t4 = (i & 15) * 4;
        float4 x0 = *(const float4*)(qg + (size_t)(2 * c2)     * SEQ + t0 + t4);
        float4 x1 = *(const float4*)(qg + (size_t)(2 * c2 + 1) * SEQ + t0 + t4);
        uint4 hw, lw;
        split2(x0.x, x1.x, hw.x, lw.x);
        split2(x0.y, x1.y, hw.y, lw.y);
        split2(x0.z, x1.z, hw.z, lw.z);
        split2(x0.w, x1.w, hw.w, lw.w);
        *(uint4*)(smu + QHI + c2 * Q_ST + t4) = hw;
        *(uint4*)(smu + QLO + c2 * Q_ST + t4) = lw;
    }

    const float CSC = 0.18033688011112042f;   // 0.125 * log2(e)
    float m0 = -INFINITY, m1 = -INFINITY, l0 = 0.f, l1 = 0.f;
    float co[8][4];
#pragma unroll
    for (int nf = 0; nf < 8; nf++)
#pragma unroll
        for (int j = 0; j < 4; j++) co[nf][j] = 0.f;

    for (int st = 0; st < NTILES; ++st) {
        const int s0 = st * BS;

        // ---- Load K: channel-pairs -> K2[c2][s] hi/lo (32 x 128) ----
        for (int i = tid; i < 1024; i += NTHREADS) {
            int c2 = i >> 5, s4 = (i & 31) * 4;
            float4 x0 = *(const float4*)(kg + (size_t)(2 * c2)     * SEQ + s0 + s4);
            float4 x1 = *(const float4*)(kg + (size_t)(2 * c2 + 1) * SEQ + s0 + s4);
            uint4 hw, lw;
            split2(x0.x, x1.x, hw.x, lw.x);
            split2(x0.y, x1.y, hw.y, lw.y);
            split2(x0.z, x1.z, hw.z, lw.z);
            split2(x0.w, x1.w, hw.w, lw.w);
            *(uint4*)(smu + KHI + c2 * K_ST + s4) = hw;
            *(uint4*)(smu + KLO + c2 * K_ST + s4) = lw;
        }
        // ---- Load V: s-pairs -> V2[c][s2] hi/lo (64 x 64) ----
        for (int i = tid; i < 2048; i += NTHREADS) {
            int c = i >> 5, s4 = (i & 31) * 4;
            float4 x = *(const float4*)(vg + (size_t)c * SEQ + s0 + s4);
            uint2 hw, lw;
            split2(x.x, x.y, hw.x, lw.x);
            split2(x.z, x.w, hw.y, lw.y);
            *(uint2*)(smu + VHI + c * V_ST + s4 / 2) = hw;
            *(uint2*)(smu + VLO + c * V_ST + s4 / 2) = lw;
        }
        __syncthreads();

        // ---- S = Q^T K  (3-term bf16 split; warp: 16t x 128s) ----
        float cs[16][4];
#pragma unroll
        for (int nf = 0; nf < 16; nf++)
#pragma unroll
            for (int j = 0; j < 4; j++) cs[nf][j] = 0.f;

#pragma unroll
        for (int kb = 0; kb < 4; kb++) {
            const int r0 = kb * 8 + q4;
            unsigned ahi[4], alo[4];
            ahi[0] = smu[QHI + r0 * Q_ST + tb + g];
            ahi[1] = smu[QHI + r0 * Q_ST + tb + g + 8];
            ahi[2] = smu[QHI + (r0 + 4) * Q_ST + tb + g];
            ahi[3] = smu[QHI + (r0 + 4) * Q_ST + tb + g + 8];
            alo[0] = smu[QLO + r0 * Q_ST + tb + g];
            alo[1] = smu[QLO + r0 * Q_ST + tb + g + 8];
            alo[2] = smu[QLO + (r0 + 4) * Q_ST + tb + g];
            alo[3] = smu[QLO + (r0 + 4) * Q_ST + tb + g + 8];
#pragma unroll
            for (int nf = 0; nf < 16; nf++) {
                const int sc = nf * 8 + g;
                unsigned bhi[2], blo[2];
                bhi[0] = smu[KHI + r0 * K_ST + sc];
                bhi[1] = smu[KHI + (r0 + 4) * K_ST + sc];
                blo[0] = smu[KLO + r0 * K_ST + sc];
                blo[1] = smu[KLO + (r0 + 4) * K_ST + sc];
                mma_bf16(cs[nf], ahi, bhi);
                mma_bf16(cs[nf], ahi, blo);
                mma_bf16(cs[nf], alo, bhi);
            }
        }

        // ---- online softmax in exp2 domain (rows tb+g, tb+g+8) ----
        float mx0 = -INFINITY, mx1 = -INFINITY;
#pragma unroll
        for (int nf = 0; nf < 16; nf++) {
#pragma unroll
            for (int j = 0; j < 4; j++) cs[nf][j] *= CSC;
            mx0 = fmaxf(mx0, fmaxf(cs[nf][0], cs[nf][1]));
            mx1 = fmaxf(mx1, fmaxf(cs[nf][2], cs[nf][3]));
        }
        mx0 = fmaxf(mx0, __shfl_xor_sync(0xffffffffu, mx0, 1));
        mx0 = fmaxf(mx0, __shfl_xor_sync(0xffffffffu, mx0, 2));
        mx1 = fmaxf(mx1, __shfl_xor_sync(0xffffffffu, mx1, 1));
        mx1 = fmaxf(mx1, __shfl_xor_sync(0xffffffffu, mx1, 2));

        const float mn0 = fmaxf(m0, mx0);
        const float mn1 = fmaxf(m1, mx1);
        const float al0 = exp2f(m0 - mn0);
        const float al1 = exp2f(m1 - mn1);
        m0 = mn0; m1 = mn1;

        float rs0 = 0.f, rs1 = 0.f;
#pragma unroll
        for (int nf = 0; nf < 16; nf++) {
            cs[nf][0] = exp2f(cs[nf][0] - mn0);
            cs[nf][1] = exp2f(cs[nf][1] - mn0);
            cs[nf][2] = exp2f(cs[nf][2] - mn1);
            cs[nf][3] = exp2f(cs[nf][3] - mn1);
            rs0 += cs[nf][0] + cs[nf][1];
            rs1 += cs[nf][2] + cs[nf][3];
        }
        l0 = l0 * al0 + rs0;
        l1 = l1 * al1 + rs1;
#pragma unroll
        for (int nf = 0; nf < 8; nf++) {
            co[nf][0] *= al0; co[nf][1] *= al0;
            co[nf][2] *= al1; co[nf][3] *= al1;
        }

        // ---- O += P * V^T : P in registers (hi/lo), V hi/lo ----
#pragma unroll
        for (int kb = 0; kb < 8; kb++) {
            unsigned ahi[4], alo[4];
            split2(cs[2 * kb][0],     cs[2 * kb][1],     ahi[0], alo[0]);
            split2(cs[2 * kb][2],     cs[2 * kb][3],     ahi[1], alo[1]);
            split2(cs[2 * kb + 1][0], cs[2 * kb + 1][1], ahi[2], alo[2]);
            split2(cs[2 * kb + 1][2], cs[2 * kb + 1][3], ahi[3], alo[3]);
#pragma unroll
            for (int nf = 0; nf < 8; nf++) {
                const int c = nf * 8 + g;
                unsigned bhi[2], blo[2];
                bhi[0] = smu[VHI + c * V_ST + kb * 8 + q4];
                bhi[1] = smu[VHI + c * V_ST + kb * 8 + 4 + q4];
                blo[0] = smu[VLO + c * V_ST + kb * 8 + q4];
                blo[1] = smu[VLO + c * V_ST + kb * 8 + 4 + q4];
                mma_bf16(co[nf], ahi, bhi);
                mma_bf16(co[nf], ahi, blo);
                mma_bf16(co[nf], alo, bhi);
            }
        }
        __syncthreads();   // K/V regions reused next tile
    }

    // ---- finalize rows ----
    l0 += __shfl_xor_sync(0xffffffffu, l0, 1);
    l0 += __shfl_xor_sync(0xffffffffu, l0, 2);
    l1 += __shfl_xor_sync(0xffffffffu, l1, 1);
    l1 += __shfl_xor_sync(0xffffffffu, l1, 2);
    const float inv0 = 1.f / l0;
    const float inv1 = 1.f / l1;
#pragma unroll
    for (int nf = 0; nf < 8; nf++) {
        co[nf][0] *= inv0; co[nf][1] *= inv0;
        co[nf][2] *= inv1; co[nf][3] *= inv1;
    }

    // ---- epilogue: stage O as [c][t] floats (reuse Q region) ----
#pragma unroll
    for (int nf = 0; nf < 8; nf++) {
        const int c = nf * 8 + 2 * q4;
        smf[(c)     * OST + tb + g]     = co[nf][0];
        smf[(c + 1) * OST + tb + g]     = co[nf][1];
        smf[(c)     * OST + tb + g + 8] = co[nf][2];
        smf[(c + 1) * OST + tb + g + 8] = co[nf][3];
    }
    __syncthreads();

    for (int i = tid; i < 1024; i += NTHREADS) {
        int c = i >> 4, t4 = (i & 15) * 4;
        *(float4*)(og + (size_t)c * SEQ + t0 + t4) =
            *(const float4*)(smf + c * OST + t4);
    }
}

extern "C" void kernel_launch(void* const* d_in, const int* in_sizes, int n_in,
                              void* d_out, int out_size) {
    (void)in_sizes; (void)n_in; (void)out_size;
    const float* qkv = (const float*)d_in[0];
    float* out = (float*)d_out;

    cudaFuncSetAttribute(qkv_attn_v6,
                         cudaFuncAttributeMaxDynamicSharedMemorySize, SMEM_BYTES);

    dim3 grid(SEQ / BT, 128);   // (16 t-tiles, 128 heads)
    qkv_attn_v6<<<grid, NTHREADS, SMEM_BYTES>>>(qkv, out);
}

// round 7
// speedup vs baseline: 2.7335x; 1.4869x over previous
#include <cuda_runtime.h>
#include <math.h>

#define CH      64
#define SEQ     1024
#define BT      64
#define BS      128
#define NTILES  8
#define NTHREADS 128

// smem word (u32) layout
#define Q_ST 72
#define K_ST 136
#define V_ST 68
#define QHI 0
#define QLO (QHI + 32 * Q_ST)
#define KHI (QLO + 32 * Q_ST)
#define KLO (KHI + 32 * K_ST)
#define VHI (KLO + 32 * K_ST)
#define VLO (VHI + 64 * V_ST)
#define SMEM_WORDS (VLO + 64 * V_ST)   // 22016
#define SMEM_BYTES (SMEM_WORDS * 4)    // 88064
#define OST 68

__device__ __forceinline__ void split2(float f0, float f1, unsigned& hi, unsigned& lo) {
    unsigned h;
    asm("cvt.rn.bf16x2.f32 %0, %1, %2;" : "=r"(h) : "f"(f1), "f"(f0));
    float h0 = __uint_as_float(h << 16);
    float h1 = __uint_as_float(h & 0xffff0000u);
    float r0 = f0 - h0;
    float r1 = f1 - h1;
    asm("cvt.rn.bf16x2.f32 %0, %1, %2;" : "=r"(lo) : "f"(r1), "f"(r0));
    hi = h;
}

__device__ __forceinline__ void mma_bf16(float* d, const unsigned* a, const unsigned* b) {
    asm volatile(
        "mma.sync.aligned.m16n8k16.row.col.f32.bf16.bf16.f32 "
        "{%0,%1,%2,%3}, {%4,%5,%6,%7}, {%8,%9}, {%0,%1,%2,%3};\n"
        : "+f"(d[0]), "+f"(d[1]), "+f"(d[2]), "+f"(d[3])
        : "r"(a[0]), "r"(a[1]), "r"(a[2]), "r"(a[3]), "r"(b[0]), "r"(b[1]));
}

__global__ __launch_bounds__(NTHREADS, 2)
void qkv_attn_v7(const float* __restrict__ qkv, float* __restrict__ out) {
    extern __shared__ unsigned smu[];
    float* smf = (float*)smu;

    const int t0 = blockIdx.x * BT;
    const int hb = blockIdx.y;
    const int b  = hb >> 4;
    const int h  = hb & 15;

    const float* qg = qkv + ((size_t)b * 3072 + (size_t)h * CH) * SEQ;
    const float* kg = qg + (size_t)1024 * SEQ;
    const float* vg = qg + (size_t)2048 * SEQ;
    float*       og = out + ((size_t)b * 1024 + (size_t)h * CH) * SEQ;

    const int tid  = threadIdx.x;
    const int wid  = tid >> 5;
    const int lane = tid & 31;
    const int g    = lane >> 2;
    const int q4   = lane & 3;
    const int tb   = wid * 16;

    const float CSC = 0.18033688011112042f;   // 0.125 * log2(e), folded into Q

    // ---- Load Q once (scaled by CSC): channel-pairs -> Q2[c2][t] hi/lo ----
    {
        float4 xa[4], xb[4];
#pragma unroll
        for (int j = 0; j < 4; j++) {
            int i = tid + j * NTHREADS;
            int c2 = i >> 4, t4 = (i & 15) * 4;
            xa[j] = *(const float4*)(qg + (size_t)(2 * c2)     * SEQ + t0 + t4);
            xb[j] = *(const float4*)(qg + (size_t)(2 * c2 + 1) * SEQ + t0 + t4);
        }
#pragma unroll
        for (int j = 0; j < 4; j++) {
            int i = tid + j * NTHREADS;
            int c2 = i >> 4, t4 = (i & 15) * 4;
            uint4 hw, lw;
            split2(xa[j].x * CSC, xb[j].x * CSC, hw.x, lw.x);
            split2(xa[j].y * CSC, xb[j].y * CSC, hw.y, lw.y);
            split2(xa[j].z * CSC, xb[j].z * CSC, hw.z, lw.z);
            split2(xa[j].w * CSC, xb[j].w * CSC, hw.w, lw.w);
            *(uint4*)(smu + QHI + c2 * Q_ST + t4) = hw;
            *(uint4*)(smu + QLO + c2 * Q_ST + t4) = lw;
        }
    }

    float m0 = -INFINITY, m1 = -INFINITY, l0 = 0.f, l1 = 0.f;
    float co[8][4];
#pragma unroll
    for (int nf = 0; nf < 8; nf++)
#pragma unroll
        for (int j = 0; j < 4; j++) co[nf][j] = 0.f;

    for (int st = 0; st < NTILES; ++st) {
        const int s0 = st * BS;

        // ---- Load K: channel-pairs, 2 chunks of 4 (8 LDG.128 in flight) ----
#pragma unroll
        for (int ch = 0; ch < 2; ch++) {
            float4 xa[4], xb[4];
#pragma unroll
            for (int j = 0; j < 4; j++) {
                int i = tid + (ch * 4 + j) * NTHREADS;
                int c2 = i >> 5, s4 = (i & 31) * 4;
                xa[j] = *(const float4*)(kg + (size_t)(2 * c2)     * SEQ + s0 + s4);
                xb[j] = *(const float4*)(kg + (size_t)(2 * c2 + 1) * SEQ + s0 + s4);
            }
#pragma unroll
            for (int j = 0; j < 4; j++) {
                int i = tid + (ch * 4 + j) * NTHREADS;
                int c2 = i >> 5, s4 = (i & 31) * 4;
                uint4 hw, lw;
                split2(xa[j].x, xb[j].x, hw.x, lw.x);
                split2(xa[j].y, xb[j].y, hw.y, lw.y);
                split2(xa[j].z, xb[j].z, hw.z, lw.z);
                split2(xa[j].w, xb[j].w, hw.w, lw.w);
                *(uint4*)(smu + KHI + c2 * K_ST + s4) = hw;
                *(uint4*)(smu + KLO + c2 * K_ST + s4) = lw;
            }
        }
        // ---- Load V: s-pairs, 2 chunks of 8 ----
#pragma unroll
        for (int ch = 0; ch < 2; ch++) {
            float4 x[8];
#pragma unroll
            for (int j = 0; j < 8; j++) {
                int i = tid + (ch * 8 + j) * NTHREADS;
                int c = i >> 5, s4 = (i & 31) * 4;
                x[j] = *(const float4*)(vg + (size_t)c * SEQ + s0 + s4);
            }
#pragma unroll
            for (int j = 0; j < 8; j++) {
                int i = tid + (ch * 8 + j) * NTHREADS;
                int c = i >> 5, s4 = (i & 31) * 4;
                uint2 hw, lw;
                split2(x[j].x, x[j].y, hw.x, lw.x);
                split2(x[j].z, x[j].w, hw.y, lw.y);
                *(uint2*)(smu + VHI + c * V_ST + s4 / 2) = hw;
                *(uint2*)(smu + VLO + c * V_ST + s4 / 2) = lw;
            }
        }
        __syncthreads();

        // ---- S = Q^T K  (3-term split, nf-pair interleaved) ----
        float cs[16][4];
#pragma unroll
        for (int nf = 0; nf < 16; nf++)
#pragma unroll
            for (int j = 0; j < 4; j++) cs[nf][j] = 0.f;

#pragma unroll
        for (int kb = 0; kb < 4; kb++) {
            const int r0 = kb * 8 + q4;
            unsigned ahi[4], alo[4];
            ahi[0] = smu[QHI + r0 * Q_ST + tb + g];
            ahi[1] = smu[QHI + r0 * Q_ST + tb + g + 8];
            ahi[2] = smu[QHI + (r0 + 4) * Q_ST + tb + g];
            ahi[3] = smu[QHI + (r0 + 4) * Q_ST + tb + g + 8];
            alo[0] = smu[QLO + r0 * Q_ST + tb + g];
            alo[1] = smu[QLO + r0 * Q_ST + tb + g + 8];
            alo[2] = smu[QLO + (r0 + 4) * Q_ST + tb + g];
            alo[3] = smu[QLO + (r0 + 4) * Q_ST + tb + g + 8];
#pragma unroll
            for (int nfp = 0; nfp < 8; nfp++) {
                const int nf0 = 2 * nfp, nf1 = 2 * nfp + 1;
                const int sc0 = nf0 * 8 + g, sc1 = nf1 * 8 + g;
                unsigned b0h[2], b0l[2], b1h[2], b1l[2];
                b0h[0] = smu[KHI + r0 * K_ST + sc0];
                b0h[1] = smu[KHI + (r0 + 4) * K_ST + sc0];
                b1h[0] = smu[KHI + r0 * K_ST + sc1];
                b1h[1] = smu[KHI + (r0 + 4) * K_ST + sc1];
                b0l[0] = smu[KLO + r0 * K_ST + sc0];
                b0l[1] = smu[KLO + (r0 + 4) * K_ST + sc0];
                b1l[0] = smu[KLO + r0 * K_ST + sc1];
                b1l[1] = smu[KLO + (r0 + 4) * K_ST + sc1];
                mma_bf16(cs[nf0], ahi, b0h);
                mma_bf16(cs[nf1], ahi, b1h);
                mma_bf16(cs[nf0], ahi, b0l);
                mma_bf16(cs[nf1], ahi, b1l);
                mma_bf16(cs[nf0], alo, b0h);
                mma_bf16(cs[nf1], alo, b1h);
            }
        }

        // ---- online softmax in exp2 domain (scale already folded into Q) ----
        float mx0 = -INFINITY, mx1 = -INFINITY;
#pragma unroll
        for (int nf = 0; nf < 16; nf++) {
            mx0 = fmaxf(mx0, fmaxf(cs[nf][0], cs[nf][1]));
            mx1 = fmaxf(mx1, fmaxf(cs[nf][2], cs[nf][3]));
        }
        mx0 = fmaxf(mx0, __shfl_xor_sync(0xffffffffu, mx0, 1));
        mx0 = fmaxf(mx0, __shfl_xor_sync(0xffffffffu, mx0, 2));
        mx1 = fmaxf(mx1, __shfl_xor_sync(0xffffffffu, mx1, 1));
        mx1 = fmaxf(mx1, __shfl_xor_sync(0xffffffffu, mx1, 2));

        const float mn0 = fmaxf(m0, mx0);
        const float mn1 = fmaxf(m1, mx1);
        const float al0 = exp2f(m0 - mn0);
        const float al1 = exp2f(m1 - mn1);
        m0 = mn0; m1 = mn1;

        float rs0 = 0.f, rs1 = 0.f;
#pragma unroll
        for (int nf = 0; nf < 16; nf++) {
            cs[nf][0] = exp2f(cs[nf][0] - mn0);
            cs[nf][1] = exp2f(cs[nf][1] - mn0);
            cs[nf][2] = exp2f(cs[nf][2] - mn1);
            cs[nf][3] = exp2f(cs[nf][3] - mn1);
            rs0 += cs[nf][0] + cs[nf][1];
            rs1 += cs[nf][2] + cs[nf][3];
        }
        l0 = l0 * al0 + rs0;
        l1 = l1 * al1 + rs1;
#pragma unroll
        for (int nf = 0; nf < 8; nf++) {
            co[nf][0] *= al0; co[nf][1] *= al0;
            co[nf][2] *= al1; co[nf][3] *= al1;
        }

        // ---- O += P * V^T  (3-term split, nf-pair interleaved) ----
#pragma unroll
        for (int kb = 0; kb < 8; kb++) {
            unsigned ahi[4], alo[4];
            split2(cs[2 * kb][0],     cs[2 * kb][1],     ahi[0], alo[0]);
            split2(cs[2 * kb][2],     cs[2 * kb][3],     ahi[1], alo[1]);
            split2(cs[2 * kb + 1][0], cs[2 * kb + 1][1], ahi[2], alo[2]);
            split2(cs[2 * kb + 1][2], cs[2 * kb + 1][3], ahi[3], alo[3]);
#pragma unroll
            for (int nfp = 0; nfp < 4; nfp++) {
                const int nf0 = 2 * nfp, nf1 = 2 * nfp + 1;
                const int c0 = nf0 * 8 + g, c1 = nf1 * 8 + g;
                unsigned b0h[2], b0l[2], b1h[2], b1l[2];
                b0h[0] = smu[VHI + c0 * V_ST + kb * 8 + q4];
                b0h[1] = smu[VHI + c0 * V_ST + kb * 8 + 4 + q4];
                b1h[0] = smu[VHI + c1 * V_ST + kb * 8 + q4];
                b1h[1] = smu[VHI + c1 * V_ST + kb * 8 + 4 + q4];
                b0l[0] = smu[VLO + c0 * V_ST + kb * 8 + q4];
                b0l[1] = smu[VLO + c0 * V_ST + kb * 8 + 4 + q4];
                b1l[0] = smu[VLO + c1 * V_ST + kb * 8 + q4];
                b1l[1] = smu[VLO + c1 * V_ST + kb * 8 + 4 + q4];
                mma_bf16(co[nf0], ahi, b0h);
                mma_bf16(co[nf1], ahi, b1h);
                mma_bf16(co[nf0], ahi, b0l);
                mma_bf16(co[nf1], ahi, b1l);
                mma_bf16(co[nf0], alo, b0h);
                mma_bf16(co[nf1], alo, b1h);
            }
        }
        __syncthreads();
    }

    // ---- finalize rows ----
    l0 += __shfl_xor_sync(0xffffffffu, l0, 1);
    l0 += __shfl_xor_sync(0xffffffffu, l0, 2);
    l1 += __shfl_xor_sync(0xffffffffu, l1, 1);
    l1 += __shfl_xor_sync(0xffffffffu, l1, 2);
    const float inv0 = 1.f / l0;
    const float inv1 = 1.f / l1;
#pragma unroll
    for (int nf = 0; nf < 8; nf++) {
        co[nf][0] *= inv0; co[nf][1] *= inv0;
        co[nf][2] *= inv1; co[nf][3] *= inv1;
    }

    // ---- epilogue: stage O as [c][t] floats (reuse Q region) ----
#pragma unroll
    for (int nf = 0; nf < 8; nf++) {
        const int c = nf * 8 + 2 * q4;
        smf[(c)     * OST + tb + g]     = co[nf][0];
        smf[(c + 1) * OST + tb + g]     = co[nf][1];
        smf[(c)     * OST + tb + g + 8] = co[nf][2];
        smf[(c + 1) * OST + tb + g + 8] = co[nf][3];
    }
    __syncthreads();

    for (int i = tid; i < 1024; i += NTHREADS) {
        int c = i >> 4, t4 = (i & 15) * 4;
        *(float4*)(og + (size_t)c * SEQ + t0 + t4) =
            *(const float4*)(smf + c * OST + t4);
    }
}

extern "C" void kernel_launch(void* const* d_in, const int* in_sizes, int n_in,
                              void* d_out, int out_size) {
    (void)in_sizes; (void)n_in; (void)out_size;
    const float* qkv = (const float*)d_in[0];
    float* out = (float*)d_out;

    cudaFuncSetAttribute(qkv_attn_v7,
                         cudaFuncAttributeMaxDynamicSharedMemorySize, SMEM_BYTES);

    dim3 grid(SEQ / BT, 128);
    qkv_attn_v7<<<grid, NTHREADS, SMEM_BYTES>>>(qkv, out);
}